// round 16
// baseline (speedup 1.0000x reference)
#include <cuda_runtime.h>
#include <cuda_fp16.h>
#include <math.h>
#include <stdint.h>

// Problem constants
#define Bz 8
#define Tz 1024
#define Cz 768
#define NHz 12
#define HDz 64
#define Mz (Bz*Tz)        // 8192
#define NBLK 24           // 32-half gmem blocks per K
#define NSTG 12           // 64-half stages per K (2 blocks each)

// Scratch (device globals; no allocation).
__device__ uint32_t g_qw[Bz*NHz*Tz*HDz/2];
__device__ uint32_t g_kw[Bz*NHz*Tz*HDz/2];
__device__ uint32_t g_vw[Bz*NHz*Tz*HDz/2];
__device__ uint32_t g_xf[64*NBLK*2048];          // x, A-fragment-major
__device__ uint32_t g_yf[64*NBLK*2048];          // y, A-fragment-major
__device__ uint32_t g_waf[18*NBLK*2048];         // w_attn, B-fragment-major
__device__ uint32_t g_wpf[6*NBLK*2048];          // w_proj, B-fragment-major

__device__ __forceinline__ uint32_t pack2(float lo, float hi) {
    __half2 h = __floats2half2_rn(lo, hi);
    return *reinterpret_cast<uint32_t*>(&h);
}

__device__ __forceinline__ void mma_f16(
    float& d0, float& d1, float& d2, float& d3,
    uint32_t a0, uint32_t a1, uint32_t a2, uint32_t a3,
    uint32_t b0, uint32_t b1)
{
    asm volatile(
        "mma.sync.aligned.m16n8k16.row.col.f32.f16.f16.f32 "
        "{%0,%1,%2,%3}, {%4,%5,%6,%7}, {%8,%9}, {%0,%1,%2,%3};\n"
        : "+f"(d0), "+f"(d1), "+f"(d2), "+f"(d3)
        : "r"(a0), "r"(a1), "r"(a2), "r"(a3), "r"(b0), "r"(b1));
}

__device__ __forceinline__ uint32_t smem_u32(const void* p) {
    uint32_t a;
    asm("{ .reg .u64 t; cvta.to.shared.u64 t, %1; cvt.u32.u64 %0, t; }"
        : "=r"(a) : "l"(p));
    return a;
}

__device__ __forceinline__ void cp16(uint32_t dst, const uint32_t* src) {
    asm volatile("cp.async.ca.shared.global [%0], [%1], 16;\n"
                 :: "r"(dst), "l"(src));
}
#define CP_COMMIT() asm volatile("cp.async.commit_group;\n" ::: "memory")
#define CP_WAIT(n)  asm volatile("cp.async.wait_group %0;\n" :: "n"(n) : "memory")

// ---------------------------------------------------------------------------
// Pre-pass: fragment-major gmem images (R12/R14 version).
// ---------------------------------------------------------------------------
__global__ __launch_bounds__(256) void conv_xf(
    const float* __restrict__ x, uint32_t* __restrict__ out)
{
    const int t = blockIdx.x * 256 + threadIdx.x;
    const int u = t & 511, block = t >> 9;
    const int T = u >> 5, lanep = u & 31;
    const int lane = lanep ^ ((lanep >> 3) & 3);
    const int gr = lane >> 2, tig = lane & 3;
    const int mt = T >> 1, ks = T & 1;
    const int bm = block / NBLK, s = block - bm * NBLK;
    const int m0 = bm*128 + mt*16 + gr;
    const int kw = s*16 + ks*8 + tig;
    const float* r0 = x + (size_t)m0 * Cz;
    const float* r8 = r0 + 8 * Cz;
    float2 a = *(const float2*)(r0 + 2*kw);
    float2 b = *(const float2*)(r8 + 2*kw);
    float2 c = *(const float2*)(r0 + 2*kw + 8);
    float2 d = *(const float2*)(r8 + 2*kw + 8);
    uint4 w = make_uint4(pack2(a.x, a.y), pack2(b.x, b.y),
                         pack2(c.x, c.y), pack2(d.x, d.y));
    ((uint4*)out)[t] = w;
}

__global__ __launch_bounds__(256) void conv_wf(
    const float* __restrict__ W, uint32_t* __restrict__ out, int N)
{
    const int t = blockIdx.x * 256 + threadIdx.x;
    const int u = t & 1023, block = t >> 10;
    const int T2 = u >> 5, lane = u & 31;
    const int ks = T2 >> 4, ntile = T2 & 15;
    const int gn = lane >> 2, tig = lane & 3;
    const int bn = block / NBLK, s = block - bn * NBLK;
    const int n = bn*128 + ntile*8 + gn;
    const int kw = s*16 + ks*8 + tig;
    uint2 w;
    w.x = pack2(W[(size_t)(2*kw    )*N + n], W[(size_t)(2*kw + 1)*N + n]);
    w.y = pack2(W[(size_t)(2*kw + 8)*N + n], W[(size_t)(2*kw + 9)*N + n]);
    ((uint2*)out)[t] = w;
}

// ---------------------------------------------------------------------------
// FP16 GEMM: 128x128 CTA, K-stage 64 halves (2 fragment blocks), 2-buffer
// cp.async pipeline, 12 barriers total. smem 64 KB/CTA (same carveout as R14).
// ---------------------------------------------------------------------------
#define GS_WORDS (4*4096)   // 64 KB dynamic smem

template <int EPI>
__global__ __launch_bounds__(256, 2) void tgemm_kernel(
    const uint32_t* __restrict__ Af, const uint32_t* __restrict__ Bf,
    const float* __restrict__ bias, float* __restrict__ Cout, int N)
{
    extern __shared__ uint32_t sm[];

    const int tid  = threadIdx.x;
    const int wid  = tid >> 5;
    const int lane = tid & 31;
    const int wm   = wid & 1;
    const int wn   = wid >> 1;
    const int gr   = lane >> 2;
    const int tig  = lane & 3;
    const int bm   = blockIdx.y * 128;
    const int bn   = blockIdx.x * 128;

    // Thread covers 16 words per stage (4 cp16). A bufs @0/@4096 words;
    // B bufs @8192/@12288 words.
    const uint32_t ab = smem_u32(sm) + tid*64;
    const uint32_t bb = ab + 2*4096*4;
    const uint32_t* Abase = Af + (size_t)blockIdx.y * NBLK * 2048 + tid*16;
    const uint32_t* Bbase = Bf + (size_t)blockIdx.x * NBLK * 2048 + tid*16;

    const int aswz = (lane ^ ((lane >> 3) & 3)) * 4;
    const int boff = lane * 2;

    float acc[4][4][4];
#pragma unroll
    for (int i = 0; i < 4; ++i)
#pragma unroll
        for (int j = 0; j < 4; ++j)
#pragma unroll
            for (int r = 0; r < 4; ++r) acc[i][j][r] = 0.f;

    // Prologue: stage 0 -> buf 0
#pragma unroll
    for (int j = 0; j < 4; ++j) {
        cp16(ab + j*16, Abase + j*4);
        cp16(bb + j*16, Bbase + j*4);
    }
    CP_COMMIT();

    for (int s = 0; s < NSTG; ++s) {
        CP_WAIT(0);            // stage s resident (had full prior stage to land)
        __syncthreads();       // all warps done with buf s&1^1 (prev consume)

        // Issue stage s+1 into buf^1 (consumed during iter s-1; barrier above
        // guarantees every warp finished reading it).
        if (s + 1 < NSTG) {
            const int nb = (s + 1) & 1;
            const uint32_t ad = ab + nb*4096*4;
            const uint32_t bd = bb + nb*4096*4;
            const uint32_t* As = Abase + (s + 1)*4096;
            const uint32_t* Bs = Bbase + (s + 1)*4096;
#pragma unroll
            for (int j = 0; j < 4; ++j) {
                cp16(ad + j*16, As + j*4);
                cp16(bd + j*16, Bs + j*4);
            }
            CP_COMMIT();
        }

        // Consume buf s&1: 2 blocks x 2 ks-steps (order == R14 block order)
        const int buf = s & 1;
        const uint32_t* Abuf = sm + buf*4096;
        const uint32_t* Bbuf = sm + 2*4096 + buf*4096;
#pragma unroll
        for (int kk = 0; kk < 4; ++kk) {
            const int blk2 = kk >> 1, ks = kk & 1;
            const uint32_t* Ab = Abuf + blk2*2048;
            const uint32_t* Bb = Bbuf + blk2*2048;
            uint4 af[4];
#pragma unroll
            for (int mt = 0; mt < 4; ++mt)
                af[mt] = *(const uint4*)&Ab[((wm*4 + mt)*2 + ks)*128 + aswz];
            uint2 bf[4];
#pragma unroll
            for (int nt = 0; nt < 4; ++nt)
                bf[nt] = *(const uint2*)&Bb[(ks*16 + wn*4 + nt)*64 + boff];
#pragma unroll
            for (int mt = 0; mt < 4; ++mt)
#pragma unroll
                for (int nt = 0; nt < 4; ++nt)
                    mma_f16(acc[mt][nt][0], acc[mt][nt][1],
                            acc[mt][nt][2], acc[mt][nt][3],
                            af[mt].x, af[mt].y, af[mt].z, af[mt].w,
                            bf[nt].x, bf[nt].y);
        }
    }

    // ---- Epilogue (identical numerics to R14) ----
#pragma unroll
    for (int mt = 0; mt < 4; ++mt) {
#pragma unroll
        for (int nt = 0; nt < 4; ++nt) {
            const int nb2 = bn + wn*32 + nt*8 + 2*tig;
#pragma unroll
            for (int half = 0; half < 2; ++half) {
                const int m = bm + wm*64 + mt*16 + gr + half*8;
                const float v0 = acc[mt][nt][half*2 + 0] + bias[nb2 + 0];
                const float v1 = acc[mt][nt][half*2 + 1] + bias[nb2 + 1];
                if (EPI == 0) {
                    const int which = nb2 / Cz;
                    const int c = nb2 - which * Cz;
                    const int h = c >> 6;
                    const int d = c & 63;
                    const int b = m >> 10;
                    const int t = m & 1023;
                    uint32_t* dst = (which == 0) ? g_qw : (which == 1) ? g_kw : g_vw;
                    dst[(((size_t)(b*NHz + h) << 10) + t)*32 + (d >> 1)] = pack2(v0, v1);
                } else {
                    *(float2*)&Cout[(size_t)m*N + nb2] = make_float2(v0, v1);
                }
            }
        }
    }
}

// ---------------------------------------------------------------------------
// Flash attention fp16 (R14 version: K via cp.async overlapping tile compute,
// V via LDG + byte_perm). Epilogue writes g_yf A-fragment-major.
// ---------------------------------------------------------------------------
#define KWS 36
#define VWS 72
#define KTW (64*KWS)
#define VTW (32*VWS)

__global__ __launch_bounds__(256) void flash2_kernel(
    const uint32_t* __restrict__ gq, const uint32_t* __restrict__ gk,
    const uint32_t* __restrict__ gv, uint32_t* __restrict__ gy)
{
    __shared__ __align__(16) uint32_t Kw[2][KTW];
    __shared__ __align__(16) uint32_t Vw[2][VTW];

    const int bh  = blockIdx.x;
    const int qb  = 7 - blockIdx.y;
    const int tid = threadIdx.x;
    const int wid = tid >> 5, lane = tid & 31;
    const int gr  = lane >> 2;
    const int tig = lane & 3;

    const int qrow0 = qb*128 + wid*16;
    const float scale = 0.125f;

    const uint32_t* qw = gq + ((size_t)bh*Tz + qrow0) * 32;
    uint32_t qf[4][4];
#pragma unroll
    for (int kb = 0; kb < 4; ++kb) {
        qf[kb][0] = qw[(size_t)gr*32     + kb*8 + tig    ];
        qf[kb][1] = qw[(size_t)(gr+8)*32 + kb*8 + tig    ];
        qf[kb][2] = qw[(size_t)gr*32     + kb*8 + tig + 4];
        qf[kb][3] = qw[(size_t)(gr+8)*32 + kb*8 + tig + 4];
    }

    float O[8][4];
#pragma unroll
    for (int nt = 0; nt < 8; ++nt)
#pragma unroll
        for (int r = 0; r < 4; ++r) O[nt][r] = 0.f;
    float m0 = -INFINITY, m1 = -INFINITY, l0 = 0.f, l1 = 0.f;

    const int ntiles = 2*qb + 2;

    const int sr  = tid >> 2;
    const int sdw = (tid & 3) * 8;
    const int vp  = tid >> 3;
    const int vdc = (tid & 7) * 8;
    const uint32_t* kbase0 = gk + (size_t)bh*Tz*32;
    const uint32_t* vbase0 = gv + (size_t)bh*Tz*32;

    const uint32_t kdst0 = smem_u32(&Kw[0][0]) + (sr*KWS + sdw)*4;

    {
        const uint32_t* kp = kbase0 + (size_t)sr*32 + sdw;
        cp16(kdst0,      kp);
        cp16(kdst0 + 16, kp + 4);
        CP_COMMIT();

        const uint32_t* vpl = vbase0 + (size_t)(2*vp)*32 + (vdc >> 1);
        uint4 u0 = *(const uint4*)(vpl);
        uint4 u1 = *(const uint4*)(vpl + 32);
        uint4 wA = make_uint4(__byte_perm(u0.x, u1.x, 0x5410),
                              __byte_perm(u0.x, u1.x, 0x7632),
                              __byte_perm(u0.y, u1.y, 0x5410),
                              __byte_perm(u0.y, u1.y, 0x7632));
        uint4 wB = make_uint4(__byte_perm(u0.z, u1.z, 0x5410),
                              __byte_perm(u0.z, u1.z, 0x7632),
                              __byte_perm(u0.w, u1.w, 0x5410),
                              __byte_perm(u0.w, u1.w, 0x7632));
        *(uint4*)&Vw[0][vp*VWS + vdc    ] = wA;
        *(uint4*)&Vw[0][vp*VWS + vdc + 4] = wB;
    }
    CP_WAIT(0);
    __syncthreads();

    for (int kt = 0; kt < ntiles; ++kt) {
        const int cur = kt & 1;
        const bool more = (kt + 1 < ntiles);

        uint4 u0, u1;
        if (more) {
            const int nb = cur ^ 1;
            const uint32_t* kp = kbase0 + ((size_t)(kt+1)*64 + sr)*32 + sdw;
            const uint32_t kd = kdst0 + nb*(KTW*4);
            cp16(kd,      kp);
            cp16(kd + 16, kp + 4);
            CP_COMMIT();
            const uint32_t* vpl = vbase0 + ((size_t)(kt+1)*64 + 2*vp)*32 + (vdc >> 1);
            u0 = *(const uint4*)(vpl);
            u1 = *(const uint4*)(vpl + 32);
        }

        if (kt*64 <= qrow0 + 15) {
            const uint32_t* Ksb = Kw[cur];
            const uint32_t* Vsb = Vw[cur];

            float sacc[8][4];
#pragma unroll
            for (int nt = 0; nt < 8; ++nt)
#pragma unroll
                for (int r = 0; r < 4; ++r) sacc[nt][r] = 0.f;

#pragma unroll
            for (int kb = 0; kb < 4; ++kb) {
#pragma unroll
                for (int nt = 0; nt < 8; ++nt) {
                    uint32_t b0 = Ksb[(nt*8 + gr)*KWS + kb*8 + tig    ];
                    uint32_t b1 = Ksb[(nt*8 + gr)*KWS + kb*8 + tig + 4];
                    mma_f16(sacc[nt][0], sacc[nt][1], sacc[nt][2], sacc[nt][3],
                            qf[kb][0], qf[kb][1], qf[kb][2], qf[kb][3],
                            b0, b1);
                }
            }

            const bool bnd = (kt*64 + 63 > qrow0);
            if (bnd) {
                const int r0 = qrow0 + gr, r1 = qrow0 + gr + 8;
#pragma unroll
                for (int nt = 0; nt < 8; ++nt) {
                    const int c0 = kt*64 + nt*8 + 2*tig;
                    sacc[nt][0] = (c0     > r0) ? -1e30f : sacc[nt][0]*scale;
                    sacc[nt][1] = (c0 + 1 > r0) ? -1e30f : sacc[nt][1]*scale;
                    sacc[nt][2] = (c0     > r1) ? -1e30f : sacc[nt][2]*scale;
                    sacc[nt][3] = (c0 + 1 > r1) ? -1e30f : sacc[nt][3]*scale;
                }
            } else {
#pragma unroll
                for (int nt = 0; nt < 8; ++nt)
#pragma unroll
                    for (int r = 0; r < 4; ++r) sacc[nt][r] *= scale;
            }

            float mx0 = -INFINITY, mx1 = -INFINITY;
#pragma unroll
            for (int nt = 0; nt < 8; ++nt) {
                mx0 = fmaxf(mx0, fmaxf(sacc[nt][0], sacc[nt][1]));
                mx1 = fmaxf(mx1, fmaxf(sacc[nt][2], sacc[nt][3]));
            }
            mx0 = fmaxf(mx0, __shfl_xor_sync(0xffffffffu, mx0, 1));
            mx0 = fmaxf(mx0, __shfl_xor_sync(0xffffffffu, mx0, 2));
            mx1 = fmaxf(mx1, __shfl_xor_sync(0xffffffffu, mx1, 1));
            mx1 = fmaxf(mx1, __shfl_xor_sync(0xffffffffu, mx1, 2));

            const float mn0 = fmaxf(m0, mx0);
            const float mn1 = fmaxf(m1, mx1);
            const float a0 = __expf(m0 - mn0);
            const float a1 = __expf(m1 - mn1);
            m0 = mn0; m1 = mn1;

            float s0 = 0.f, s1 = 0.f;
#pragma unroll
            for (int nt = 0; nt < 8; ++nt) {
                sacc[nt][0] = __expf(sacc[nt][0] - mn0);
                sacc[nt][1] = __expf(sacc[nt][1] - mn0);
                sacc[nt][2] = __expf(sacc[nt][2] - mn1);
                sacc[nt][3] = __expf(sacc[nt][3] - mn1);
                s0 += sacc[nt][0] + sacc[nt][1];
                s1 += sacc[nt][2] + sacc[nt][3];
            }
            s0 += __shfl_xor_sync(0xffffffffu, s0, 1);
            s0 += __shfl_xor_sync(0xffffffffu, s0, 2);
            s1 += __shfl_xor_sync(0xffffffffu, s1, 1);
            s1 += __shfl_xor_sync(0xffffffffu, s1, 2);
            l0 = l0*a0 + s0;
            l1 = l1*a1 + s1;

#pragma unroll
            for (int nt = 0; nt < 8; ++nt) {
                O[nt][0] *= a0;  O[nt][1] *= a0;
                O[nt][2] *= a1;  O[nt][3] *= a1;
            }

#pragma unroll
            for (int kb = 0; kb < 4; ++kb) {
                const uint32_t pa0 = pack2(sacc[2*kb  ][0], sacc[2*kb  ][1]);
                const uint32_t pa1 = pack2(sacc[2*kb  ][2], sacc[2*kb  ][3]);
                const uint32_t pa2 = pack2(sacc[2*kb+1][0], sacc[2*kb+1][1]);
                const uint32_t pa3 = pack2(sacc[2*kb+1][2], sacc[2*kb+1][3]);
#pragma unroll
                for (int nt = 0; nt < 8; ++nt) {
                    uint32_t b0 = Vsb[(kb*8 + tig    )*VWS + nt*8 + gr];
                    uint32_t b1 = Vsb[(kb*8 + tig + 4)*VWS + nt*8 + gr];
                    mma_f16(O[nt][0], O[nt][1], O[nt][2], O[nt][3],
                            pa0, pa1, pa2, pa3, b0, b1);
                }
            }
        }

        if (more) {
            const int nb = cur ^ 1;
            uint4 wA = make_uint4(__byte_perm(u0.x, u1.x, 0x5410),
                                  __byte_perm(u0.x, u1.x, 0x7632),
                                  __byte_perm(u0.y, u1.y, 0x5410),
                                  __byte_perm(u0.y, u1.y, 0x7632));
            uint4 wB = make_uint4(__byte_perm(u0.z, u1.z, 0x5410),
                                  __byte_perm(u0.z, u1.z, 0x7632),
                                  __byte_perm(u0.w, u1.w, 0x5410),
                                  __byte_perm(u0.w, u1.w, 0x7632));
            *(uint4*)&Vw[nb][vp*VWS + vdc    ] = wA;
            *(uint4*)&Vw[nb][vp*VWS + vdc + 4] = wB;
            CP_WAIT(0);
        }
        __syncthreads();
    }

    // ---- Epilogue: write O as tgemm<1> A-fragments into g_yf ----
    const int b = bh / NHz;
    const int h = bh % NHz;
    const float inv0 = 1.f / l0;
    const float inv1 = 1.f / l1;
    const int bm24 = ((b << 3) + qb) * NBLK;
    const int swzo = (lane ^ ((lane >> 3) & 3)) * 4;
#pragma unroll
    for (int sh = 0; sh < 2; ++sh) {
#pragma unroll
        for (int ks = 0; ks < 2; ++ks) {
            const int s  = 2*h + sh;
            const int nt = sh*4 + ks*2;
            uint4 w;
            w.x = pack2(O[nt  ][0]*inv0, O[nt  ][1]*inv0);
            w.y = pack2(O[nt  ][2]*inv1, O[nt  ][3]*inv1);
            w.z = pack2(O[nt+1][0]*inv0, O[nt+1][1]*inv0);
            w.w = pack2(O[nt+1][2]*inv1, O[nt+1][3]*inv1);
            *(uint4*)&gy[((size_t)(bm24 + s))*2048 + (wid*2 + ks)*128 + swzo] = w;
        }
    }
}

// ---------------------------------------------------------------------------
extern "C" void kernel_launch(void* const* d_in, const int* in_sizes, int n_in,
                              void* d_out, int out_size)
{
    (void)in_sizes; (void)n_in; (void)out_size;
    const float* x      = (const float*)d_in[0];
    const float* w_attn = (const float*)d_in[1];
    const float* b_attn = (const float*)d_in[2];
    const float* w_proj = (const float*)d_in[3];
    const float* b_proj = (const float*)d_in[4];
    float* out = (float*)d_out;

    uint32_t *pq, *pk, *pv, *pxf, *pyf, *pwa, *pwp;
    cudaGetSymbolAddress((void**)&pq,  g_qw);
    cudaGetSymbolAddress((void**)&pk,  g_kw);
    cudaGetSymbolAddress((void**)&pv,  g_vw);
    cudaGetSymbolAddress((void**)&pxf, g_xf);
    cudaGetSymbolAddress((void**)&pyf, g_yf);
    cudaGetSymbolAddress((void**)&pwa, g_waf);
    cudaGetSymbolAddress((void**)&pwp, g_wpf);

    const int gemm_smem = GS_WORDS * (int)sizeof(uint32_t);   // 64 KB
    cudaFuncSetAttribute(tgemm_kernel<0>,
                         cudaFuncAttributeMaxDynamicSharedMemorySize, gemm_smem);
    cudaFuncSetAttribute(tgemm_kernel<1>,
                         cudaFuncAttributeMaxDynamicSharedMemorySize, gemm_smem);

    // 0) Pre-pass: fragment-major images
    conv_xf<<<3072, 256>>>(x, pxf);
    conv_wf<<<1728, 256>>>(w_attn, pwa, 3*Cz);
    conv_wf<<<576,  256>>>(w_proj, pwp, Cz);

    // 1) QKV = x @ w_attn + b_attn, scatter half2 q/k/v
    {
        dim3 grid(3*Cz/128, Mz/128);   // (18, 64)
        tgemm_kernel<0><<<grid, 256, gemm_smem>>>(pxf, pwa, b_attn, nullptr, 3*Cz);
    }
    // 2) Flash attention -> g_yf (fragment-major)
    {
        dim3 grid(Bz*NHz, Tz/128);
        flash2_kernel<<<grid, 256>>>(pq, pk, pv, pyf);
    }
    // 3) out = y @ w_proj + b_proj (f32 out)
    {
        dim3 grid(Cz/128, Mz/128);     // (6, 64)
        tgemm_kernel<1><<<grid, 256, gemm_smem>>>(pyf, pwp, b_proj, out, Cz);
    }
}

// round 17
// speedup vs baseline: 1.1568x; 1.1568x over previous
#include <cuda_runtime.h>
#include <cuda_fp16.h>
#include <math.h>
#include <stdint.h>

// Problem constants
#define Bz 8
#define Tz 1024
#define Cz 768
#define NHz 12
#define HDz 64
#define Mz (Bz*Tz)        // 8192
#define NSTG 24           // 32-half stages per K

// Scratch (device globals; no allocation).
__device__ uint32_t g_qw[Bz*NHz*Tz*HDz/2];
__device__ uint32_t g_kw[Bz*NHz*Tz*HDz/2];
__device__ uint32_t g_vw[Bz*NHz*Tz*HDz/2];
__device__ uint32_t g_xf[64*NSTG*2048];          // x, A-fragment-major
__device__ uint32_t g_yf[64*NSTG*2048];          // y, A-fragment-major
__device__ uint32_t g_waf[18*NSTG*2048];         // w_attn, B-fragment-major
__device__ uint32_t g_wpf[6*NSTG*2048];          // w_proj, B-fragment-major

__device__ __forceinline__ uint32_t pack2(float lo, float hi) {
    __half2 h = __floats2half2_rn(lo, hi);
    return *reinterpret_cast<uint32_t*>(&h);
}

__device__ __forceinline__ void mma_f16(
    float& d0, float& d1, float& d2, float& d3,
    uint32_t a0, uint32_t a1, uint32_t a2, uint32_t a3,
    uint32_t b0, uint32_t b1)
{
    asm volatile(
        "mma.sync.aligned.m16n8k16.row.col.f32.f16.f16.f32 "
        "{%0,%1,%2,%3}, {%4,%5,%6,%7}, {%8,%9}, {%0,%1,%2,%3};\n"
        : "+f"(d0), "+f"(d1), "+f"(d2), "+f"(d3)
        : "r"(a0), "r"(a1), "r"(a2), "r"(a3), "r"(b0), "r"(b1));
}

__device__ __forceinline__ uint32_t smem_u32(const void* p) {
    uint32_t a;
    asm("{ .reg .u64 t; cvta.to.shared.u64 t, %1; cvt.u32.u64 %0, t; }"
        : "=r"(a) : "l"(p));
    return a;
}

__device__ __forceinline__ void cp16(uint32_t dst, const uint32_t* src) {
    asm volatile("cp.async.ca.shared.global [%0], [%1], 16;\n"
                 :: "r"(dst), "l"(src));
}
#define CP_COMMIT() asm volatile("cp.async.commit_group;\n" ::: "memory")
#define CP_WAIT(n)  asm volatile("cp.async.wait_group %0;\n" :: "n"(n) : "memory")

// ---------------------------------------------------------------------------
// Fused pre-pass: ONE launch builds all three fragment-major images.
// Block ranges: [0,3072) x -> g_xf; [3072,4800) w_attn -> g_waf;
//               [4800,5376) w_proj -> g_wpf. Inner logic identical to R14.
// ---------------------------------------------------------------------------
__device__ __forceinline__ void conv_x_body(
    const float* __restrict__ x, uint32_t* __restrict__ out, int t)
{
    const int u = t & 511, block = t >> 9;
    const int T = u >> 5, lanep = u & 31;
    const int lane = lanep ^ ((lanep >> 3) & 3);
    const int gr = lane >> 2, tig = lane & 3;
    const int mt = T >> 1, ks = T & 1;
    const int bm = block / NSTG, s = block - bm * NSTG;
    const int m0 = bm*128 + mt*16 + gr;
    const int kw = s*16 + ks*8 + tig;
    const float* r0 = x + (size_t)m0 * Cz;
    const float* r8 = r0 + 8 * Cz;
    float2 a = *(const float2*)(r0 + 2*kw);
    float2 b = *(const float2*)(r8 + 2*kw);
    float2 c = *(const float2*)(r0 + 2*kw + 8);
    float2 d = *(const float2*)(r8 + 2*kw + 8);
    uint4 w = make_uint4(pack2(a.x, a.y), pack2(b.x, b.y),
                         pack2(c.x, c.y), pack2(d.x, d.y));
    ((uint4*)out)[t] = w;
}

__device__ __forceinline__ void conv_w_body(
    const float* __restrict__ W, uint32_t* __restrict__ out, int N, int t)
{
    const int u = t & 1023, block = t >> 10;
    const int T2 = u >> 5, lane = u & 31;
    const int ks = T2 >> 4, ntile = T2 & 15;
    const int gn = lane >> 2, tig = lane & 3;
    const int bn = block / NSTG, s = block - bn * NSTG;
    const int n = bn*128 + ntile*8 + gn;
    const int kw = s*16 + ks*8 + tig;
    uint2 w;
    w.x = pack2(W[(size_t)(2*kw    )*N + n], W[(size_t)(2*kw + 1)*N + n]);
    w.y = pack2(W[(size_t)(2*kw + 8)*N + n], W[(size_t)(2*kw + 9)*N + n]);
    ((uint2*)out)[t] = w;
}

__global__ __launch_bounds__(256) void conv_all(
    const float* __restrict__ x,  uint32_t* __restrict__ oxf,
    const float* __restrict__ wa, uint32_t* __restrict__ owa,
    const float* __restrict__ wp, uint32_t* __restrict__ owp)
{
    const int blk = blockIdx.x;
    if (blk < 3072) {
        conv_x_body(x, oxf, blk*256 + threadIdx.x);
    } else if (blk < 4800) {
        conv_w_body(wa, owa, 3*Cz, (blk - 3072)*256 + threadIdx.x);
    } else {
        conv_w_body(wp, owp, Cz, (blk - 4800)*256 + threadIdx.x);
    }
}

// ---------------------------------------------------------------------------
// FP16 GEMM (exact R14: K-stage 32, 4-buffer cp.async ring, 64 KB smem).
// ---------------------------------------------------------------------------
#define GS_WORDS (8*2048)   // 64 KB dynamic smem

template <int EPI>
__global__ __launch_bounds__(256, 2) void tgemm_kernel(
    const uint32_t* __restrict__ Af, const uint32_t* __restrict__ Bf,
    const float* __restrict__ bias, float* __restrict__ Cout, int N)
{
    extern __shared__ uint32_t sm[];

    const int tid  = threadIdx.x;
    const int wid  = tid >> 5;
    const int lane = tid & 31;
    const int wm   = wid & 1;
    const int wn   = wid >> 1;
    const int gr   = lane >> 2;
    const int tig  = lane & 3;
    const int bm   = blockIdx.y * 128;
    const int bn   = blockIdx.x * 128;

    const uint32_t ab = smem_u32(sm) + tid*32;
    const uint32_t bb = ab + 4*2048*4;
    const uint32_t* Abase = Af + (size_t)blockIdx.y * NSTG * 2048 + tid*8;
    const uint32_t* Bbase = Bf + (size_t)blockIdx.x * NSTG * 2048 + tid*8;

    const int aswz = (lane ^ ((lane >> 3) & 3)) * 4;
    const int boff = lane * 2;

    float acc[4][4][4];
#pragma unroll
    for (int i = 0; i < 4; ++i)
#pragma unroll
        for (int j = 0; j < 4; ++j)
#pragma unroll
            for (int r = 0; r < 4; ++r) acc[i][j][r] = 0.f;

#pragma unroll
    for (int p = 0; p < 3; ++p) {
        const uint32_t ad = ab + p*2048*4;
        const uint32_t bd = bb + p*2048*4;
        cp16(ad,      Abase + p*2048);
        cp16(ad + 16, Abase + p*2048 + 4);
        cp16(bd,      Bbase + p*2048);
        cp16(bd + 16, Bbase + p*2048 + 4);
        CP_COMMIT();
    }

    for (int s = 0; s < NSTG; ++s) {
        if (s < NSTG - 2)      CP_WAIT(2);
        else if (s < NSTG - 1) CP_WAIT(1);
        else                   CP_WAIT(0);
        __syncthreads();

        const int buf = s & 3;
        const uint32_t* Ab = sm + buf*2048;
        const uint32_t* Bb = sm + 4*2048 + buf*2048;

#pragma unroll
        for (int ks = 0; ks < 2; ++ks) {
            uint4 af[4];
#pragma unroll
            for (int mt = 0; mt < 4; ++mt)
                af[mt] = *(const uint4*)&Ab[((wm*4 + mt)*2 + ks)*128 + aswz];
            uint2 bf[4];
#pragma unroll
            for (int nt = 0; nt < 4; ++nt)
                bf[nt] = *(const uint2*)&Bb[(ks*16 + wn*4 + nt)*64 + boff];
#pragma unroll
            for (int mt = 0; mt < 4; ++mt)
#pragma unroll
                for (int nt = 0; nt < 4; ++nt)
                    mma_f16(acc[mt][nt][0], acc[mt][nt][1],
                            acc[mt][nt][2], acc[mt][nt][3],
                            af[mt].x, af[mt].y, af[mt].z, af[mt].w,
                            bf[nt].x, bf[nt].y);
        }

        if (s + 3 < NSTG) {
            const int nb = (s + 3) & 3;
            const uint32_t ad = ab + nb*2048*4;
            const uint32_t bd = bb + nb*2048*4;
            cp16(ad,      Abase + (s + 3)*2048);
            cp16(ad + 16, Abase + (s + 3)*2048 + 4);
            cp16(bd,      Bbase + (s + 3)*2048);
            cp16(bd + 16, Bbase + (s + 3)*2048 + 4);
            CP_COMMIT();
        }
    }

    // ---- Epilogue ----
#pragma unroll
    for (int mt = 0; mt < 4; ++mt) {
#pragma unroll
        for (int nt = 0; nt < 4; ++nt) {
            const int nb2 = bn + wn*32 + nt*8 + 2*tig;
#pragma unroll
            for (int half = 0; half < 2; ++half) {
                const int m = bm + wm*64 + mt*16 + gr + half*8;
                const float v0 = acc[mt][nt][half*2 + 0] + bias[nb2 + 0];
                const float v1 = acc[mt][nt][half*2 + 1] + bias[nb2 + 1];
                if (EPI == 0) {
                    const int which = nb2 / Cz;
                    const int c = nb2 - which * Cz;
                    const int h = c >> 6;
                    const int d = c & 63;
                    const int b = m >> 10;
                    const int t = m & 1023;
                    uint32_t* dst = (which == 0) ? g_qw : (which == 1) ? g_kw : g_vw;
                    dst[(((size_t)(b*NHz + h) << 10) + t)*32 + (d >> 1)] = pack2(v0, v1);
                } else {
                    *(float2*)&Cout[(size_t)m*N + nb2] = make_float2(v0, v1);
                }
            }
        }
    }
}

// ---------------------------------------------------------------------------
// Flash attention fp16 (exact R14).
// ---------------------------------------------------------------------------
#define KWS 36
#define VWS 72
#define KTW (64*KWS)
#define VTW (32*VWS)

__global__ __launch_bounds__(256) void flash2_kernel(
    const uint32_t* __restrict__ gq, const uint32_t* __restrict__ gk,
    const uint32_t* __restrict__ gv, uint32_t* __restrict__ gy)
{
    __shared__ __align__(16) uint32_t Kw[2][KTW];
    __shared__ __align__(16) uint32_t Vw[2][VTW];

    const int bh  = blockIdx.x;
    const int qb  = 7 - blockIdx.y;
    const int tid = threadIdx.x;
    const int wid = tid >> 5, lane = tid & 31;
    const int gr  = lane >> 2;
    const int tig = lane & 3;

    const int qrow0 = qb*128 + wid*16;
    const float scale = 0.125f;

    const uint32_t* qw = gq + ((size_t)bh*Tz + qrow0) * 32;
    uint32_t qf[4][4];
#pragma unroll
    for (int kb = 0; kb < 4; ++kb) {
        qf[kb][0] = qw[(size_t)gr*32     + kb*8 + tig    ];
        qf[kb][1] = qw[(size_t)(gr+8)*32 + kb*8 + tig    ];
        qf[kb][2] = qw[(size_t)gr*32     + kb*8 + tig + 4];
        qf[kb][3] = qw[(size_t)(gr+8)*32 + kb*8 + tig + 4];
    }

    float O[8][4];
#pragma unroll
    for (int nt = 0; nt < 8; ++nt)
#pragma unroll
        for (int r = 0; r < 4; ++r) O[nt][r] = 0.f;
    float m0 = -INFINITY, m1 = -INFINITY, l0 = 0.f, l1 = 0.f;

    const int ntiles = 2*qb + 2;

    const int sr  = tid >> 2;
    const int sdw = (tid & 3) * 8;
    const int vp  = tid >> 3;
    const int vdc = (tid & 7) * 8;
    const uint32_t* kbase0 = gk + (size_t)bh*Tz*32;
    const uint32_t* vbase0 = gv + (size_t)bh*Tz*32;

    const uint32_t kdst0 = smem_u32(&Kw[0][0]) + (sr*KWS + sdw)*4;

    {
        const uint32_t* kp = kbase0 + (size_t)sr*32 + sdw;
        cp16(kdst0,      kp);
        cp16(kdst0 + 16, kp + 4);
        CP_COMMIT();

        const uint32_t* vpl = vbase0 + (size_t)(2*vp)*32 + (vdc >> 1);
        uint4 u0 = *(const uint4*)(vpl);
        uint4 u1 = *(const uint4*)(vpl + 32);
        uint4 wA = make_uint4(__byte_perm(u0.x, u1.x, 0x5410),
                              __byte_perm(u0.x, u1.x, 0x7632),
                              __byte_perm(u0.y, u1.y, 0x5410),
                              __byte_perm(u0.y, u1.y, 0x7632));
        uint4 wB = make_uint4(__byte_perm(u0.z, u1.z, 0x5410),
                              __byte_perm(u0.z, u1.z, 0x7632),
                              __byte_perm(u0.w, u1.w, 0x5410),
                              __byte_perm(u0.w, u1.w, 0x7632));
        *(uint4*)&Vw[0][vp*VWS + vdc    ] = wA;
        *(uint4*)&Vw[0][vp*VWS + vdc + 4] = wB;
    }
    CP_WAIT(0);
    __syncthreads();

    for (int kt = 0; kt < ntiles; ++kt) {
        const int cur = kt & 1;
        const bool more = (kt + 1 < ntiles);

        uint4 u0, u1;
        if (more) {
            const int nb = cur ^ 1;
            const uint32_t* kp = kbase0 + ((size_t)(kt+1)*64 + sr)*32 + sdw;
            const uint32_t kd = kdst0 + nb*(KTW*4);
            cp16(kd,      kp);
            cp16(kd + 16, kp + 4);
            CP_COMMIT();
            const uint32_t* vpl = vbase0 + ((size_t)(kt+1)*64 + 2*vp)*32 + (vdc >> 1);
            u0 = *(const uint4*)(vpl);
            u1 = *(const uint4*)(vpl + 32);
        }

        if (kt*64 <= qrow0 + 15) {
            const uint32_t* Ksb = Kw[cur];
            const uint32_t* Vsb = Vw[cur];

            float sacc[8][4];
#pragma unroll
            for (int nt = 0; nt < 8; ++nt)
#pragma unroll
                for (int r = 0; r < 4; ++r) sacc[nt][r] = 0.f;

#pragma unroll
            for (int kb = 0; kb < 4; ++kb) {
#pragma unroll
                for (int nt = 0; nt < 8; ++nt) {
                    uint32_t b0 = Ksb[(nt*8 + gr)*KWS + kb*8 + tig    ];
                    uint32_t b1 = Ksb[(nt*8 + gr)*KWS + kb*8 + tig + 4];
                    mma_f16(sacc[nt][0], sacc[nt][1], sacc[nt][2], sacc[nt][3],
                            qf[kb][0], qf[kb][1], qf[kb][2], qf[kb][3],
                            b0, b1);
                }
            }

            const bool bnd = (kt*64 + 63 > qrow0);
            if (bnd) {
                const int r0 = qrow0 + gr, r1 = qrow0 + gr + 8;
#pragma unroll
                for (int nt = 0; nt < 8; ++nt) {
                    const int c0 = kt*64 + nt*8 + 2*tig;
                    sacc[nt][0] = (c0     > r0) ? -1e30f : sacc[nt][0]*scale;
                    sacc[nt][1] = (c0 + 1 > r0) ? -1e30f : sacc[nt][1]*scale;
                    sacc[nt][2] = (c0     > r1) ? -1e30f : sacc[nt][2]*scale;
                    sacc[nt][3] = (c0 + 1 > r1) ? -1e30f : sacc[nt][3]*scale;
                }
            } else {
#pragma unroll
                for (int nt = 0; nt < 8; ++nt)
#pragma unroll
                    for (int r = 0; r < 4; ++r) sacc[nt][r] *= scale;
            }

            float mx0 = -INFINITY, mx1 = -INFINITY;
#pragma unroll
            for (int nt = 0; nt < 8; ++nt) {
                mx0 = fmaxf(mx0, fmaxf(sacc[nt][0], sacc[nt][1]));
                mx1 = fmaxf(mx1, fmaxf(sacc[nt][2], sacc[nt][3]));
            }
            mx0 = fmaxf(mx0, __shfl_xor_sync(0xffffffffu, mx0, 1));
            mx0 = fmaxf(mx0, __shfl_xor_sync(0xffffffffu, mx0, 2));
            mx1 = fmaxf(mx1, __shfl_xor_sync(0xffffffffu, mx1, 1));
            mx1 = fmaxf(mx1, __shfl_xor_sync(0xffffffffu, mx1, 2));

            const float mn0 = fmaxf(m0, mx0);
            const float mn1 = fmaxf(m1, mx1);
            const float a0 = __expf(m0 - mn0);
            const float a1 = __expf(m1 - mn1);
            m0 = mn0; m1 = mn1;

            float s0 = 0.f, s1 = 0.f;
#pragma unroll
            for (int nt = 0; nt < 8; ++nt) {
                sacc[nt][0] = __expf(sacc[nt][0] - mn0);
                sacc[nt][1] = __expf(sacc[nt][1] - mn0);
                sacc[nt][2] = __expf(sacc[nt][2] - mn1);
                sacc[nt][3] = __expf(sacc[nt][3] - mn1);
                s0 += sacc[nt][0] + sacc[nt][1];
                s1 += sacc[nt][2] + sacc[nt][3];
            }
            s0 += __shfl_xor_sync(0xffffffffu, s0, 1);
            s0 += __shfl_xor_sync(0xffffffffu, s0, 2);
            s1 += __shfl_xor_sync(0xffffffffu, s1, 1);
            s1 += __shfl_xor_sync(0xffffffffu, s1, 2);
            l0 = l0*a0 + s0;
            l1 = l1*a1 + s1;

#pragma unroll
            for (int nt = 0; nt < 8; ++nt) {
                O[nt][0] *= a0;  O[nt][1] *= a0;
                O[nt][2] *= a1;  O[nt][3] *= a1;
            }

#pragma unroll
            for (int kb = 0; kb < 4; ++kb) {
                const uint32_t pa0 = pack2(sacc[2*kb  ][0], sacc[2*kb  ][1]);
                const uint32_t pa1 = pack2(sacc[2*kb  ][2], sacc[2*kb  ][3]);
                const uint32_t pa2 = pack2(sacc[2*kb+1][0], sacc[2*kb+1][1]);
                const uint32_t pa3 = pack2(sacc[2*kb+1][2], sacc[2*kb+1][3]);
#pragma unroll
                for (int nt = 0; nt < 8; ++nt) {
                    uint32_t b0 = Vsb[(kb*8 + tig    )*VWS + nt*8 + gr];
                    uint32_t b1 = Vsb[(kb*8 + tig + 4)*VWS + nt*8 + gr];
                    mma_f16(O[nt][0], O[nt][1], O[nt][2], O[nt][3],
                            pa0, pa1, pa2, pa3, b0, b1);
                }
            }
        }

        if (more) {
            const int nb = cur ^ 1;
            uint4 wA = make_uint4(__byte_perm(u0.x, u1.x, 0x5410),
                                  __byte_perm(u0.x, u1.x, 0x7632),
                                  __byte_perm(u0.y, u1.y, 0x5410),
                                  __byte_perm(u0.y, u1.y, 0x7632));
            uint4 wB = make_uint4(__byte_perm(u0.z, u1.z, 0x5410),
                                  __byte_perm(u0.z, u1.z, 0x7632),
                                  __byte_perm(u0.w, u1.w, 0x5410),
                                  __byte_perm(u0.w, u1.w, 0x7632));
            *(uint4*)&Vw[nb][vp*VWS + vdc    ] = wA;
            *(uint4*)&Vw[nb][vp*VWS + vdc + 4] = wB;
            CP_WAIT(0);
        }
        __syncthreads();
    }

    // ---- Epilogue: write O as tgemm<1> A-fragments into g_yf ----
    const int b = bh / NHz;
    const int h = bh % NHz;
    const float inv0 = 1.f / l0;
    const float inv1 = 1.f / l1;
    const int bm24 = ((b << 3) + qb) * NSTG;
    const int swzo = (lane ^ ((lane >> 3) & 3)) * 4;
#pragma unroll
    for (int sh = 0; sh < 2; ++sh) {
#pragma unroll
        for (int ks = 0; ks < 2; ++ks) {
            const int s  = 2*h + sh;
            const int nt = sh*4 + ks*2;
            uint4 w;
            w.x = pack2(O[nt  ][0]*inv0, O[nt  ][1]*inv0);
            w.y = pack2(O[nt  ][2]*inv1, O[nt  ][3]*inv1);
            w.z = pack2(O[nt+1][0]*inv0, O[nt+1][1]*inv0);
            w.w = pack2(O[nt+1][2]*inv1, O[nt+1][3]*inv1);
            *(uint4*)&gy[((size_t)(bm24 + s))*2048 + (wid*2 + ks)*128 + swzo] = w;
        }
    }
}

// ---------------------------------------------------------------------------
extern "C" void kernel_launch(void* const* d_in, const int* in_sizes, int n_in,
                              void* d_out, int out_size)
{
    (void)in_sizes; (void)n_in; (void)out_size;
    const float* x      = (const float*)d_in[0];
    const float* w_attn = (const float*)d_in[1];
    const float* b_attn = (const float*)d_in[2];
    const float* w_proj = (const float*)d_in[3];
    const float* b_proj = (const float*)d_in[4];
    float* out = (float*)d_out;

    uint32_t *pq, *pk, *pv, *pxf, *pyf, *pwa, *pwp;
    cudaGetSymbolAddress((void**)&pq,  g_qw);
    cudaGetSymbolAddress((void**)&pk,  g_kw);
    cudaGetSymbolAddress((void**)&pv,  g_vw);
    cudaGetSymbolAddress((void**)&pxf, g_xf);
    cudaGetSymbolAddress((void**)&pyf, g_yf);
    cudaGetSymbolAddress((void**)&pwa, g_waf);
    cudaGetSymbolAddress((void**)&pwp, g_wpf);

    const int gemm_smem = GS_WORDS * (int)sizeof(uint32_t);   // 64 KB
    cudaFuncSetAttribute(tgemm_kernel<0>,
                         cudaFuncAttributeMaxDynamicSharedMemorySize, gemm_smem);
    cudaFuncSetAttribute(tgemm_kernel<1>,
                         cudaFuncAttributeMaxDynamicSharedMemorySize, gemm_smem);

    // 0) Fused pre-pass: one launch builds all three fragment images
    conv_all<<<5376, 256>>>(x, pxf, w_attn, pwa, w_proj, pwp);

    // 1) QKV = x @ w_attn + b_attn, scatter half2 q/k/v
    {
        dim3 grid(3*Cz/128, Mz/128);   // (18, 64)
        tgemm_kernel<0><<<grid, 256, gemm_smem>>>(pxf, pwa, b_attn, nullptr, 3*Cz);
    }
    // 2) Flash attention -> g_yf (fragment-major)
    {
        dim3 grid(Bz*NHz, Tz/128);
        flash2_kernel<<<grid, 256>>>(pq, pk, pv, pyf);
    }
    // 3) out = y @ w_proj + b_proj (f32 out)
    {
        dim3 grid(Cz/128, Mz/128);     // (6, 64)
        tgemm_kernel<1><<<grid, 256, gemm_smem>>>(pyf, pwp, b_proj, out, Cz);
    }
}